// round 3
// baseline (speedup 1.0000x reference)
#include <cuda_runtime.h>
#include <math.h>

#define NLEVELS 16
#define TBL     (1u << 19)
#define NPTS    (64 * 64 * 64)
#define PTS_PER_BLK 64
#define THREADS 256

constexpr double SCALE_ = 1.447269237440378;

__host__ __device__ constexpr int res_of(int l) {
    double r = 16.0;
    for (int i = 0; i < l; ++i) r *= SCALE_;
    return (int)(r + 1e-6);
}

// Process 4 levels [L0, L0+4) for one point; write 8 enc values to smem row.
template<int L0>
__device__ __forceinline__
void do_levels4(float px, float py, float pz,
                const float* __restrict__ table,
                float* __restrict__ enc_row /* points at senc[p*33 + (L0/4)*8] */)
{
#pragma unroll
    for (int ll = 0; ll < 4; ++ll) {
        constexpr int dummy = 0; (void)dummy;
        const int l = L0 + ll;
        const int res =
            (l == 0)  ? res_of(0)  : (l == 1)  ? res_of(1)  :
            (l == 2)  ? res_of(2)  : (l == 3)  ? res_of(3)  :
            (l == 4)  ? res_of(4)  : (l == 5)  ? res_of(5)  :
            (l == 6)  ? res_of(6)  : (l == 7)  ? res_of(7)  :
            (l == 8)  ? res_of(8)  : (l == 9)  ? res_of(9)  :
            (l == 10) ? res_of(10) : (l == 11) ? res_of(11) :
            (l == 12) ? res_of(12) : (l == 13) ? res_of(13) :
            (l == 14) ? res_of(14) : res_of(15);
        const bool dense = ((long long)(res + 1) * (res + 1) * (res + 1) <= (long long)TBL);

        const float fres = (float)res;
        const float x = px * fres, y = py * fres, z = pz * fres;
        const float fx = floorf(x), fy = floorf(y), fz = floorf(z);
        const float tx = x - fx, ty = y - fy, tz = z - fz;
        const unsigned cx = (unsigned)fx, cy = (unsigned)fy, cz = (unsigned)fz;

        const float2* tab = (const float2*)table + (size_t)l * TBL;

        // compute all 8 indices first (independent), then 8 loads in flight
        unsigned idx[8];
#pragma unroll
        for (int c = 0; c < 8; ++c) {
            const unsigned X = cx + ((c >> 2) & 1u);
            const unsigned Y = cy + ((c >> 1) & 1u);
            const unsigned Z = cz + (c & 1u);
            unsigned id;
            if (dense) {
                const unsigned r1 = (unsigned)(res + 1);
                id = X + r1 * (Y + r1 * Z);
            } else {
                id = X ^ (Y * 2654435761u) ^ (Z * 805459861u);
            }
            idx[c] = id & (TBL - 1u);
        }
        float2 t[8];
#pragma unroll
        for (int c = 0; c < 8; ++c) t[c] = __ldg(tab + idx[c]);

        float e0 = 0.f, e1 = 0.f;
#pragma unroll
        for (int c = 0; c < 8; ++c) {
            const float wx = ((c >> 2) & 1) ? tx : 1.f - tx;
            const float wy = ((c >> 1) & 1) ? ty : 1.f - ty;
            const float wz = (c & 1)        ? tz : 1.f - tz;
            const float w = wx * wy * wz;
            e0 = fmaf(w, t[c].x, e0);
            e1 = fmaf(w, t[c].y, e1);
        }
        enc_row[2 * ll + 0] = e0;
        enc_row[2 * ll + 1] = e1;
    }
}

__global__ __launch_bounds__(THREADS, 5)
void hashgrid_mlp_kernel(const float* __restrict__ pts,
                         const float* __restrict__ table,
                         const float* __restrict__ w1,
                         const float* __restrict__ w2,
                         float* __restrict__ out)
{
    __shared__ float sw1[64 * 32];
    __shared__ float sw2[64];
    __shared__ float spts[PTS_PER_BLK * 3];
    __shared__ float senc[PTS_PER_BLK * 33];      // padded rows (33) -> conflict-free
    __shared__ float spart[PTS_PER_BLK * 5];      // 4 partials + pad

    const int tid = threadIdx.x;
    for (int k = tid; k < 64 * 32; k += THREADS) sw1[k] = w1[k];
    if (tid < 64) sw2[tid] = w2[tid];
    if (tid < PTS_PER_BLK * 3) spts[tid] = pts[blockIdx.x * (PTS_PER_BLK * 3) + tid];
    __syncthreads();

    const int p = tid & 63;       // point within block
    const int g = tid >> 6;       // level-group / MLP quarter (warp-uniform)

    const float px = spts[3 * p + 0];
    const float py = spts[3 * p + 1];
    const float pz = spts[3 * p + 2];

    float* enc_row = senc + p * 33 + g * 8;
    switch (g) {
        case 0: do_levels4<0>(px, py, pz, table, enc_row); break;
        case 1: do_levels4<4>(px, py, pz, table, enc_row); break;
        case 2: do_levels4<8>(px, py, pz, table, enc_row); break;
        default: do_levels4<12>(px, py, pz, table, enc_row); break;
    }
    __syncthreads();

    // ---- MLP phase: thread (p,g) computes hidden units j in [g*16, g*16+16) ----
    float enc[32];
#pragma unroll
    for (int k = 0; k < 32; ++k) enc[k] = senc[p * 33 + k];

    float acc = 0.f;
    const int jbase = g * 16;
#pragma unroll
    for (int jj = 0; jj < 16; ++jj) {
        const int j = jbase + jj;
        float h = 0.f;
        const float4* row = (const float4*)(sw1 + j * 32);
#pragma unroll
        for (int k = 0; k < 8; ++k) {
            const float4 v = row[k];
            h = fmaf(enc[4 * k + 0], v.x, h);
            h = fmaf(enc[4 * k + 1], v.y, h);
            h = fmaf(enc[4 * k + 2], v.z, h);
            h = fmaf(enc[4 * k + 3], v.w, h);
        }
        h = fmaxf(h, 0.f);
        acc = fmaf(h, sw2[j], acc);
    }
    spart[p * 5 + g] = acc;
    __syncthreads();

    if (tid < PTS_PER_BLK) {
        const float s = (spart[tid * 5 + 0] + spart[tid * 5 + 1]) +
                        (spart[tid * 5 + 2] + spart[tid * 5 + 3]);
        out[blockIdx.x * PTS_PER_BLK + tid] = 1.f / (1.f + expf(-s));
    }
}

extern "C" void kernel_launch(void* const* d_in, const int* in_sizes, int n_in,
                              void* d_out, int out_size)
{
    const float* pts   = (const float*)d_in[0];
    const float* table = (const float*)d_in[1];
    const float* w1    = (const float*)d_in[2];
    const float* w2    = (const float*)d_in[3];
    float* out = (float*)d_out;

    hashgrid_mlp_kernel<<<NPTS / PTS_PER_BLK, THREADS>>>(pts, table, w1, w2, out);
}

// round 5
// speedup vs baseline: 1.3534x; 1.3534x over previous
#include <cuda_runtime.h>
#include <math.h>

#define NLEVELS 16
#define TBL     (1u << 19)
#define NPTS    (64 * 64 * 64)

constexpr double SCALE_ = 1.447269237440378;

__host__ __device__ constexpr int res_of(int l) {
    double r = 16.0;
    for (int i = 0; i < l; ++i) r *= SCALE_;
    return (int)(r + 1e-6);
}

__global__ __launch_bounds__(256, 4)
void hashgrid_mlp_kernel(const float* __restrict__ pts,
                         const float* __restrict__ table,
                         const float* __restrict__ w1,
                         const float* __restrict__ w2,
                         float* __restrict__ out)
{
    __shared__ float sw1[64 * 32];
    __shared__ float sw2[64];

    const int tid = threadIdx.x;
    for (int k = tid; k < 64 * 32; k += 256) sw1[k] = w1[k];
    if (tid < 64) sw2[tid] = w2[tid];
    __syncthreads();

    const int i = blockIdx.x * 256 + tid;

    const float px = __ldg(pts + 3 * i + 0);
    const float py = __ldg(pts + 3 * i + 1);
    const float pz = __ldg(pts + 3 * i + 2);

    float enc[32];

    constexpr int RESA[NLEVELS] = {
        res_of(0),  res_of(1),  res_of(2),  res_of(3),
        res_of(4),  res_of(5),  res_of(6),  res_of(7),
        res_of(8),  res_of(9),  res_of(10), res_of(11),
        res_of(12), res_of(13), res_of(14), res_of(15)
    };

#pragma unroll
    for (int l = 0; l < NLEVELS; ++l) {
        const int res = RESA[l];
        const bool dense = ((long long)(res + 1) * (res + 1) * (res + 1) <= (long long)TBL);

        const float fres = (float)res;
        const float x = px * fres, y = py * fres, z = pz * fres;
        const float fx = floorf(x), fy = floorf(y), fz = floorf(z);
        const float tx = x - fx, ty = y - fy, tz = z - fz;
        const unsigned cx = (unsigned)fx, cy = (unsigned)fy, cz = (unsigned)fz;

        const float2* tab = (const float2*)table + (size_t)l * TBL;

        // 4 X-pairs: corners (cx,Y,Z) and (cx+1,Y,Z) for the 4 (Y,Z) combos.
        unsigned iA[4], iB[4];
#pragma unroll
        for (int c = 0; c < 4; ++c) {
            const unsigned Y = cy + ((c >> 1) & 1u);
            const unsigned Z = cz + (c & 1u);
            if (dense) {
                const unsigned r1 = (unsigned)(res + 1);
                const unsigned b = r1 * (Y + r1 * Z);
                iA[c] = (cx + b) & (TBL - 1u);
                iB[c] = (cx + 1u + b) & (TBL - 1u);
            } else {
                const unsigned h = (Y * 2654435761u) ^ (Z * 805459861u);
                iA[c] = (cx ^ h) & (TBL - 1u);
                iB[c] = ((cx + 1u) ^ h) & (TBL - 1u);
            }
        }

        // Always fetch the aligned 16B block holding iA (delivers iB too when
        // the pair is contained: hash with cx even -> {i, i^1}; dense with iA even).
        float4 v[4];
#pragma unroll
        for (int c = 0; c < 4; ++c)
            v[c] = __ldg((const float4*)tab + (iA[c] >> 1));

        // Predicated fallback load for iB when not in the same block.
        float2 b64[4];
        bool cont[4];
#pragma unroll
        for (int c = 0; c < 4; ++c) {
            cont[c] = ((iA[c] >> 1) == (iB[c] >> 1));
            if (!cont[c]) b64[c] = __ldg(tab + iB[c]);
        }

        float e0 = 0.f, e1 = 0.f;
#pragma unroll
        for (int c = 0; c < 4; ++c) {
            const float2 lo = make_float2(v[c].x, v[c].y);
            const float2 hi = make_float2(v[c].z, v[c].w);
            const float2 tA = (iA[c] & 1u) ? hi : lo;
            const float2 tBc = (iB[c] & 1u) ? hi : lo;
            const float2 tB = cont[c] ? tBc : b64[c];
            const float wyz = (((c >> 1) & 1) ? ty : 1.f - ty) *
                              ((c & 1) ? tz : 1.f - tz);
            const float wA = (1.f - tx) * wyz;
            const float wB = tx * wyz;
            e0 = fmaf(wA, tA.x, fmaf(wB, tB.x, e0));
            e1 = fmaf(wA, tA.y, fmaf(wB, tB.y, e1));
        }
        enc[2 * l + 0] = e0;
        enc[2 * l + 1] = e1;
    }

    // ---- tiny MLP: h = relu(enc @ w1^T); out = sigmoid(h @ w2^T) ----
    float acc = 0.f;
#pragma unroll
    for (int j = 0; j < 64; ++j) {
        float h = 0.f;
        const float4* row = (const float4*)(sw1 + j * 32);
#pragma unroll
        for (int k = 0; k < 8; ++k) {
            const float4 v = row[k];
            h = fmaf(enc[4 * k + 0], v.x, h);
            h = fmaf(enc[4 * k + 1], v.y, h);
            h = fmaf(enc[4 * k + 2], v.z, h);
            h = fmaf(enc[4 * k + 3], v.w, h);
        }
        h = fmaxf(h, 0.f);
        acc = fmaf(h, sw2[j], acc);
    }

    out[i] = 1.f / (1.f + expf(-acc));
}

extern "C" void kernel_launch(void* const* d_in, const int* in_sizes, int n_in,
                              void* d_out, int out_size)
{
    const float* pts   = (const float*)d_in[0];   // [N,3]
    const float* table = (const float*)d_in[1];   // [16, 2^19, 2]
    const float* w1    = (const float*)d_in[2];   // [64, 32]
    const float* w2    = (const float*)d_in[3];   // [1, 64]
    float* out = (float*)d_out;

    hashgrid_mlp_kernel<<<NPTS / 256, 256>>>(pts, table, w1, w2, out);
}